// round 1
// baseline (speedup 1.0000x reference)
#include <cuda_runtime.h>

// Problem geometry (fixed by the dataset)
#define M_TOTAL 256          // output channels
#define K_TOTAL 2304         // 256 * 3 * 3
#define IMG_PIX 2916         // 54 * 54
#define N_TOTAL 93312        // 32 * 2916
#define IN_HW   56
#define IN_CHW  802816       // 256*56*56 per batch image
#define OUT_HW  54

// GEMM tiling
#define BM 128
#define BN 128
#define BK 16
#define TM 8
#define TN 8
#define NTHREADS 256

// Pre-binarized, pre-transposed weights: g_wt[k][oc] = sign(w[oc][k])
__device__ float g_wt[K_TOTAL * M_TOTAL];

__global__ void binarize_kernel(const float* __restrict__ w) {
    int i = blockIdx.x * blockDim.x + threadIdx.x;   // index over [oc][k]
    if (i < M_TOTAL * K_TOTAL) {
        int oc = i / K_TOTAL;
        int k  = i - oc * K_TOTAL;
        float v = w[i];
        float s = (v > 0.0f) ? 1.0f : ((v < 0.0f) ? -1.0f : 0.0f);
        g_wt[k * M_TOTAL + oc] = s;
    }
}

__global__ __launch_bounds__(NTHREADS, 2)
void bconv_gemm(const float* __restrict__ x, float* __restrict__ out) {
    __shared__ __align__(16) float As[BK][BM];
    __shared__ __align__(16) float Bs[BK][BN];

    const int tid = threadIdx.x;
    const int m0  = blockIdx.y * BM;
    const int n0  = blockIdx.x * BN;

    // ---- loader mapping: 256 threads cover a 16x128 tile, 8 k-rows each ----
    const int lcol  = tid & 127;        // 0..127 along M (A) / N (B)
    const int lrow0 = (tid >> 7) * 8;   // 0 or 8, first of 8 k-rows

    // B-side geometry fixed per thread (its pixel column)
    const int n    = n0 + lcol;
    const int bimg = n / IMG_PIX;
    const int p    = n - bimg * IMG_PIX;
    const int oh   = p / OUT_HW;
    const int ow   = p - oh * OUT_HW;
    const float* xbase = x + (size_t)bimg * IN_CHW + oh * IN_HW + ow;

    // ---- compute mapping: 16x16 thread grid, 8x8 microtile ----
    const int m_frag = (tid >> 4) * TM;
    const int n_frag = (tid & 15) * TN;

    // accumulators: 8 rows x 4 packed f32x2 columns
    unsigned long long acc[TM][TN / 2];
#pragma unroll
    for (int i = 0; i < TM; i++)
#pragma unroll
        for (int j = 0; j < TN / 2; j++) acc[i][j] = 0ull;

    float a_pre[8], b_pre[8];

    // prologue: k-block 0 -> smem
#pragma unroll
    for (int i = 0; i < 8; i++) {
        int k = lrow0 + i;
        As[lrow0 + i][lcol] = g_wt[k * M_TOTAL + m0 + lcol];
        int c  = k / 9;
        int r  = k - c * 9;
        int kh = r / 3;
        int kw = r - kh * 3;
        Bs[lrow0 + i][lcol] = xbase[c * 3136 + kh * IN_HW + kw];
    }
    __syncthreads();

    const int KITERS = K_TOTAL / BK;  // 144
    for (int it = 0; it < KITERS; it++) {
        // prefetch next k-block into registers (overlaps with compute below)
        if (it + 1 < KITERS) {
            int kb = (it + 1) * BK;
#pragma unroll
            for (int i = 0; i < 8; i++) {
                int k = kb + lrow0 + i;
                a_pre[i] = g_wt[k * M_TOTAL + m0 + lcol];
                int c  = k / 9;
                int r  = k - c * 9;
                int kh = r / 3;
                int kw = r - kh * 3;
                b_pre[i] = xbase[c * 3136 + kh * IN_HW + kw];
            }
        }

        // compute current k-block from smem
#pragma unroll
        for (int kk = 0; kk < BK; kk++) {
            float4 a0 = *reinterpret_cast<const float4*>(&As[kk][m_frag]);
            float4 a1 = *reinterpret_cast<const float4*>(&As[kk][m_frag + 4]);
            // B fragment read directly as packed f32x2 pairs (little-endian:
            // low 32b = lower column index)
            ulonglong2 bq0 = *reinterpret_cast<const ulonglong2*>(&Bs[kk][n_frag]);
            ulonglong2 bq1 = *reinterpret_cast<const ulonglong2*>(&Bs[kk][n_frag + 4]);
            unsigned long long bp0 = bq0.x, bp1 = bq0.y, bp2 = bq1.x, bp3 = bq1.y;

            float af[8] = {a0.x, a0.y, a0.z, a0.w, a1.x, a1.y, a1.z, a1.w};
#pragma unroll
            for (int i = 0; i < TM; i++) {
                unsigned long long ap;
                asm("mov.b64 %0, {%1, %1};" : "=l"(ap) : "f"(af[i]));
                asm("fma.rn.f32x2 %0, %1, %2, %0;" : "+l"(acc[i][0]) : "l"(ap), "l"(bp0));
                asm("fma.rn.f32x2 %0, %1, %2, %0;" : "+l"(acc[i][1]) : "l"(ap), "l"(bp1));
                asm("fma.rn.f32x2 %0, %1, %2, %0;" : "+l"(acc[i][2]) : "l"(ap), "l"(bp2));
                asm("fma.rn.f32x2 %0, %1, %2, %0;" : "+l"(acc[i][3]) : "l"(ap), "l"(bp3));
            }
        }

        __syncthreads();
        if (it + 1 < KITERS) {
#pragma unroll
            for (int i = 0; i < 8; i++) {
                As[lrow0 + i][lcol] = a_pre[i];
                Bs[lrow0 + i][lcol] = b_pre[i];
            }
            __syncthreads();
        }
    }

    // ---- epilogue: unpack and scatter to NCHW output ----
    const int n_base = n0 + n_frag;
#pragma unroll
    for (int i = 0; i < TM; i++) {
        const int oc = m0 + m_frag + i;
#pragma unroll
        for (int jp = 0; jp < TN / 2; jp++) {
            float lo, hi;
            asm("mov.b64 {%0, %1}, %2;" : "=f"(lo), "=f"(hi) : "l"(acc[i][jp]));
            int nn0 = n_base + 2 * jp;
            {
                int bb = nn0 / IMG_PIX;
                int pp = nn0 - bb * IMG_PIX;
                out[((size_t)bb * M_TOTAL + oc) * IMG_PIX + pp] = lo;
            }
            {
                int nn1 = nn0 + 1;
                int bb = nn1 / IMG_PIX;
                int pp = nn1 - bb * IMG_PIX;
                out[((size_t)bb * M_TOTAL + oc) * IMG_PIX + pp] = hi;
            }
        }
    }
}

extern "C" void kernel_launch(void* const* d_in, const int* in_sizes, int n_in,
                              void* d_out, int out_size) {
    (void)in_sizes; (void)n_in; (void)out_size;
    const float* x = (const float*)d_in[0];
    const float* w = (const float*)d_in[1];
    float* out = (float*)d_out;

    binarize_kernel<<<(M_TOTAL * K_TOTAL + 255) / 256, 256>>>(w);

    dim3 grid(N_TOTAL / BN, M_TOTAL / BM);  // (729, 2)
    bconv_gemm<<<grid, NTHREADS>>>(x, out);
}

// round 3
// speedup vs baseline: 2.4752x; 2.4752x over previous
#include <cuda_runtime.h>
#include <cuda_bf16.h>
#include <cstdint>

// ---------------- problem geometry ----------------
#define M_TOTAL 256
#define K_CONV  2304          // 256*3*3
#define KD      4608          // hi/lo doubled K
#define IN_HW   56
#define IN_PLANE 3136
#define IN_CHW  802816        // 256*56*56
#define NX      25690112      // 32*802816 elements of x
#define OUT_HW  54
#define IMG_PIX 2916
#define JPAD    3072          // padded pixels per image (54 rows x 56 + pad row)

// ---------------- GEMM tiling ----------------
#define BM 128
#define BN 256
#define BK 32
#define KITERS 144            // 4608/32
#define JT_PER_IMG 12         // 3072/256

#define APAD_COLS 40          // 32 + 8 pad  (80B row stride)
#define BROW_ELEM 264         // 256 + 8 pad (528B row stride)
#define A_STAGE (128 * APAD_COLS * 2)     // 10240 B
#define B_STAGE (BK * BROW_ELEM * 2)      // 16896 B
#define STAGE_BYTES (A_STAGE + B_STAGE)   // 27136 B
#define NSTAGES 3
#define DYN_SMEM (NSTAGES * STAGE_BYTES)  // 81408 B

// ---------------- device scratch ----------------
__device__ __nv_bfloat16 g_A[M_TOTAL * KD];          // [oc][kd], halves duplicated
// [0..2] = hi with shift 0,1,2 ; [3..5] = lo with shift 0,1,2
// g_xs[s][i]   = hi/lo( x[i+s] )   (tail garbage, never used for valid outputs)
__device__ __nv_bfloat16 g_xs[6][NX + 4096];

// ---------------- helpers ----------------
__device__ __forceinline__ uint32_t smem_u32(const void* p) {
    uint32_t a;
    asm("{ .reg .u64 t; cvta.to.shared.u64 t, %1; cvt.u32.u64 %0, t; }" : "=r"(a) : "l"(p));
    return a;
}
__device__ __forceinline__ void cpa16(uint32_t dst, const void* src) {
    asm volatile("cp.async.cg.shared.global [%0], [%1], 16;" :: "r"(dst), "l"(src));
}
__device__ __forceinline__ uint32_t prmt_hi(float e, float o) {
    uint32_t r;
    asm("prmt.b32 %0, %1, %2, 0x7632;" : "=r"(r) : "r"(__float_as_uint(e)), "r"(__float_as_uint(o)));
    return r;
}
__device__ __forceinline__ uint32_t pack_bf16x2(float e, float o) {
    uint32_t r;  // low half = bf16(e), high half = bf16(o)
    asm("cvt.rn.bf16x2.f32 %0, %1, %2;" : "=r"(r) : "f"(o), "f"(e));
    return r;
}

// ---------------- prep: binarize weights ----------------
__global__ void binarize_kernel(const float* __restrict__ w) {
    int i = blockIdx.x * blockDim.x + threadIdx.x;   // over [oc][kd]
    if (i >= M_TOTAL * KD) return;
    int oc = i / KD;
    int kd = i - oc * KD;
    int k = (kd < K_CONV) ? kd : (kd - K_CONV);
    float v = w[oc * K_CONV + k];
    float s = (v > 0.0f) ? 1.0f : ((v < 0.0f) ? -1.0f : 0.0f);
    g_A[i] = __float2bfloat16(s);
}

// ---------------- prep: hi/lo split of x into 3 shifted copies each ----------------
__global__ void split_kernel(const float* __restrict__ x) {
    long i0 = ((long)blockIdx.x * blockDim.x + threadIdx.x) * 8;
    if (i0 >= NX) return;

    float v[10];
    if (i0 + 12 <= NX) {
        float4 a = *reinterpret_cast<const float4*>(x + i0);
        float4 b = *reinterpret_cast<const float4*>(x + i0 + 4);
        float4 c = *reinterpret_cast<const float4*>(x + i0 + 8);
        v[0]=a.x; v[1]=a.y; v[2]=a.z; v[3]=a.w;
        v[4]=b.x; v[5]=b.y; v[6]=b.z; v[7]=b.w;
        v[8]=c.x; v[9]=c.y;
    } else {
#pragma unroll
        for (int t = 0; t < 10; t++) v[t] = (i0 + t < NX) ? x[i0 + t] : 0.0f;
    }

    // lo = x - truncate16(x)  (exact), rounded to bf16
    float l[10];
#pragma unroll
    for (int t = 0; t < 10; t++) {
        float hv = __uint_as_float(__float_as_uint(v[t]) & 0xffff0000u);
        l[t] = v[t] - hv;
    }

    // hi pairs: even-start (0,1)(2,3)(4,5)(6,7)(8,9); odd-start (1,2)(3,4)(5,6)(7,8)
    uint32_t hp[5], hq[4], lp[5], lq[4];
#pragma unroll
    for (int j = 0; j < 5; j++) { hp[j] = prmt_hi(v[2*j], v[2*j+1]); lp[j] = pack_bf16x2(l[2*j], l[2*j+1]); }
#pragma unroll
    for (int j = 0; j < 4; j++) { hq[j] = prmt_hi(v[2*j+1], v[2*j+2]); lq[j] = pack_bf16x2(l[2*j+1], l[2*j+2]); }

    uint4 s0h = make_uint4(hp[0], hp[1], hp[2], hp[3]);
    uint4 s1h = make_uint4(hq[0], hq[1], hq[2], hq[3]);
    uint4 s2h = make_uint4(hp[1], hp[2], hp[3], hp[4]);
    uint4 s0l = make_uint4(lp[0], lp[1], lp[2], lp[3]);
    uint4 s1l = make_uint4(lq[0], lq[1], lq[2], lq[3]);
    uint4 s2l = make_uint4(lp[1], lp[2], lp[3], lp[4]);

    *reinterpret_cast<uint4*>(&g_xs[0][i0]) = s0h;
    *reinterpret_cast<uint4*>(&g_xs[1][i0]) = s1h;
    *reinterpret_cast<uint4*>(&g_xs[2][i0]) = s2h;
    *reinterpret_cast<uint4*>(&g_xs[3][i0]) = s0l;
    *reinterpret_cast<uint4*>(&g_xs[4][i0]) = s1l;
    *reinterpret_cast<uint4*>(&g_xs[5][i0]) = s2l;
}

// ---------------- GEMM: mma.sync bf16, implicit im2col via shifted copies ----------------
extern __shared__ char smem_raw[];

__global__ void __launch_bounds__(256, 1)
bconv_mma(float* __restrict__ out) {
    const int tid = threadIdx.x;
    const int lane = tid & 31;
    const int wid = tid >> 5;
    const int warp_m = wid & 1;      // 2 M-warps (64 rows each)
    const int warp_n = wid >> 1;     // 4 N-warps (64 cols each)
    const int m0 = blockIdx.x * BM;
    const int by = blockIdx.y;
    const int b  = by / JT_PER_IMG;
    const int j0 = (by - b * JT_PER_IMG) * BN;

    char* sm = smem_raw;

    float acc[4][8][4];
#pragma unroll
    for (int mi = 0; mi < 4; mi++)
#pragma unroll
        for (int ni = 0; ni < 8; ni++)
#pragma unroll
            for (int e = 0; e < 4; e++) acc[mi][ni][e] = 0.0f;

    // ---- stage loader: A 512 x 16B + B 1024 x 16B via cp.async ----
    auto load_stage = [&](int kblk, int st) {
        uint32_t abase = smem_u32(sm + st * STAGE_BYTES);
        uint32_t bbase = abase + A_STAGE;
        int k0 = kblk * BK;
#pragma unroll
        for (int i = 0; i < 2; i++) {               // A ops
            int o = tid + i * 256;
            int row = o >> 2, seg = o & 3;
            const __nv_bfloat16* src = g_A + (size_t)(m0 + row) * KD + k0 + seg * 8;
            cpa16(abase + row * 80 + seg * 16, src);
        }
#pragma unroll
        for (int i = 0; i < 4; i++) {               // B ops
            int o = tid + i * 256;
            int kr = o >> 5, seg = o & 31;
            int k = k0 + kr;
            int half = (k >= K_CONV) ? 1 : 0;
            int kk = k - half * K_CONV;
            int c  = kk / 9;
            int r9 = kk - c * 9;
            int kh = r9 / 3;
            int kw = r9 - kh * 3;
            const __nv_bfloat16* src =
                &g_xs[half * 3 + kw][(size_t)b * IN_CHW + c * IN_PLANE + kh * IN_HW + j0 + seg * 8];
            cpa16(bbase + kr * 528 + seg * 16, src);
        }
    };

    load_stage(0, 0); asm volatile("cp.async.commit_group;");
    load_stage(1, 1); asm volatile("cp.async.commit_group;");
    load_stage(2, 2); asm volatile("cp.async.commit_group;");

    int st = 0;
    for (int it = 0; it < KITERS; it++) {
        asm volatile("cp.async.wait_group 2;" ::: "memory");
        __syncthreads();

        uint32_t abase = smem_u32(sm + st * STAGE_BYTES);
        uint32_t bbase = abase + A_STAGE;

#pragma unroll
        for (int kk = 0; kk < 2; kk++) {
            uint32_t af[4][4], bf[8][2];
#pragma unroll
            for (int mi = 0; mi < 4; mi++) {
                uint32_t addr = abase + (uint32_t)((warp_m * 64 + mi * 16 + (lane & 15)) * 80
                                                   + (kk * 16 + ((lane >> 4) << 3)) * 2);
                asm volatile("ldmatrix.sync.aligned.m8n8.x4.shared.b16 {%0,%1,%2,%3}, [%4];"
                             : "=r"(af[mi][0]), "=r"(af[mi][1]), "=r"(af[mi][2]), "=r"(af[mi][3])
                             : "r"(addr));
            }
#pragma unroll
            for (int ni = 0; ni < 8; ni++) {
                uint32_t addr = bbase + (uint32_t)((kk * 16 + (lane & 15)) * 528
                                                   + (warp_n * 64 + ni * 8) * 2);
                asm volatile("ldmatrix.sync.aligned.m8n8.x2.trans.shared.b16 {%0,%1}, [%2];"
                             : "=r"(bf[ni][0]), "=r"(bf[ni][1]) : "r"(addr));
            }
#pragma unroll
            for (int mi = 0; mi < 4; mi++)
#pragma unroll
                for (int ni = 0; ni < 8; ni++) {
                    asm volatile(
                        "mma.sync.aligned.m16n8k16.row.col.f32.bf16.bf16.f32 "
                        "{%0,%1,%2,%3}, {%4,%5,%6,%7}, {%8,%9}, {%0,%1,%2,%3};"
                        : "+f"(acc[mi][ni][0]), "+f"(acc[mi][ni][1]),
                          "+f"(acc[mi][ni][2]), "+f"(acc[mi][ni][3])
                        : "r"(af[mi][0]), "r"(af[mi][1]), "r"(af[mi][2]), "r"(af[mi][3]),
                          "r"(bf[ni][0]), "r"(bf[ni][1]));
                }
        }

        __syncthreads();
        if (it + 3 < KITERS) load_stage(it + 3, st);
        asm volatile("cp.async.commit_group;");   // empty group near the tail keeps wait counts uniform

        st++; if (st == NSTAGES) st = 0;
    }

    // ---- epilogue: scatter valid pixels to NCHW output ----
#pragma unroll
    for (int mi = 0; mi < 4; mi++) {
        int m_lo = m0 + warp_m * 64 + mi * 16 + (lane >> 2);
#pragma unroll
        for (int ni = 0; ni < 8; ni++) {
            int jb = j0 + warp_n * 64 + ni * 8 + (lane & 3) * 2;
#pragma unroll
            for (int e = 0; e < 4; e++) {
                int mm = m_lo + (e >> 1) * 8;
                int j  = jb + (e & 1);
                int oh = j / IN_HW;
                int ow = j - oh * IN_HW;
                if (ow < OUT_HW && oh < OUT_HW) {
                    out[((size_t)(b * M_TOTAL + mm)) * IMG_PIX + oh * OUT_HW + ow] = acc[mi][ni][e];
                }
            }
        }
    }
}

// ---------------- launcher ----------------
extern "C" void kernel_launch(void* const* d_in, const int* in_sizes, int n_in,
                              void* d_out, int out_size) {
    (void)in_sizes; (void)n_in; (void)out_size;
    const float* x = (const float*)d_in[0];
    const float* w = (const float*)d_in[1];
    float* out = (float*)d_out;

    binarize_kernel<<<(M_TOTAL * KD + 255) / 256, 256>>>(w);
    split_kernel<<<(int)((NX / 8 + 255) / 256), 256>>>(x);

    cudaFuncSetAttribute(bconv_mma, cudaFuncAttributeMaxDynamicSharedMemorySize, DYN_SMEM);
    dim3 grid(M_TOTAL / BM, 32 * JT_PER_IMG);   // (2, 384), M fastest for B-tile L2 reuse
    bconv_mma<<<grid, 256, DYN_SMEM>>>(out);
}

// round 4
// speedup vs baseline: 4.5666x; 1.8449x over previous
#include <cuda_runtime.h>
#include <cuda_fp16.h>
#include <cstdint>

// ---------------- problem geometry ----------------
#define M_TOTAL 256
#define K_CONV  2304          // 256*3*3
#define IN_HW   56
#define IN_PLANE 3136
#define IN_CHW  802816        // 256*56*56
#define NX      25690112      // 32*802816 elements of x
#define OUT_HW  54
#define IMG_PIX 2916
#define JPAD    3072

// ---------------- GEMM tiling ----------------
#define BM 128
#define BN 256
#define BK 32
#define KITERS 72             // 2304/32
#define JT_PER_IMG 12         // 3072/256

#define A_ROW_H 40            // 32 + 8 pad halves (80B row stride)
#define B_ROW_H 264           // 256 + 8 pad halves (528B row stride)
#define A_STAGE (128 * A_ROW_H * 2)       // 10240 B
#define B_STAGE (BK * B_ROW_H * 2)        // 16896 B
#define STAGE_BYTES (A_STAGE + B_STAGE)   // 27136 B
#define NSTAGES 3
#define DYN_SMEM (NSTAGES * STAGE_BYTES)  // 81408 B

// ---------------- device scratch ----------------
__device__ __half g_A[M_TOTAL * K_CONV];          // [oc][k], sign weights in fp16
__device__ __half g_xh[3][NX + 4096];             // fp16(x) shifted by 0,1,2 elements
__device__ unsigned long long g_rowptr[K_CONV];   // per-k base pointer into g_xh

// ---------------- helpers ----------------
__device__ __forceinline__ uint32_t smem_u32(const void* p) {
    uint32_t a;
    asm("{ .reg .u64 t; cvta.to.shared.u64 t, %1; cvt.u32.u64 %0, t; }" : "=r"(a) : "l"(p));
    return a;
}
__device__ __forceinline__ void cpa16(uint32_t dst, const void* src) {
    asm volatile("cp.async.cg.shared.global [%0], [%1], 16;" :: "r"(dst), "l"(src));
}

// ---------------- prep: binarize weights to fp16 ----------------
__global__ void binarize_kernel(const float* __restrict__ w) {
    int i = blockIdx.x * blockDim.x + threadIdx.x;   // over [oc][k]
    if (i >= M_TOTAL * K_CONV) return;
    float v = w[i];
    float s = (v > 0.0f) ? 1.0f : ((v < 0.0f) ? -1.0f : 0.0f);
    g_A[i] = __float2half_rn(s);
}

// ---------------- prep: per-k row base pointers ----------------
__global__ void rowptr_kernel() {
    int k = blockIdx.x * blockDim.x + threadIdx.x;
    if (k >= K_CONV) return;
    int c  = k / 9;
    int r9 = k - c * 9;
    int kh = r9 / 3;
    int kw = r9 - kh * 3;
    g_rowptr[k] = (unsigned long long)(g_xh[kw] + c * IN_PLANE + kh * IN_HW);
}

// ---------------- prep: fp16 convert, 3 shifted copies ----------------
__global__ void split_kernel(const float* __restrict__ x) {
    long i0 = ((long)blockIdx.x * blockDim.x + threadIdx.x) * 8;
    if (i0 >= NX) return;

    float v[10];
    if (i0 + 12 <= NX) {
        float4 a = *reinterpret_cast<const float4*>(x + i0);
        float4 b = *reinterpret_cast<const float4*>(x + i0 + 4);
        float4 c = *reinterpret_cast<const float4*>(x + i0 + 8);
        v[0]=a.x; v[1]=a.y; v[2]=a.z; v[3]=a.w;
        v[4]=b.x; v[5]=b.y; v[6]=b.z; v[7]=b.w;
        v[8]=c.x; v[9]=c.y;
    } else {
#pragma unroll
        for (int t = 0; t < 10; t++) v[t] = (i0 + t < NX) ? x[i0 + t] : 0.0f;
    }

    // even-start pairs hp[j]=(2j,2j+1); odd-start hq[j]=(2j+1,2j+2)
    uint32_t hp[5], hq[4];
#pragma unroll
    for (int j = 0; j < 5; j++) {
        __half2 h = __floats2half2_rn(v[2*j], v[2*j+1]);
        hp[j] = *reinterpret_cast<uint32_t*>(&h);
    }
#pragma unroll
    for (int j = 0; j < 4; j++) {
        __half2 h = __floats2half2_rn(v[2*j+1], v[2*j+2]);
        hq[j] = *reinterpret_cast<uint32_t*>(&h);
    }

    *reinterpret_cast<uint4*>(&g_xh[0][i0]) = make_uint4(hp[0], hp[1], hp[2], hp[3]);
    *reinterpret_cast<uint4*>(&g_xh[1][i0]) = make_uint4(hq[0], hq[1], hq[2], hq[3]);
    *reinterpret_cast<uint4*>(&g_xh[2][i0]) = make_uint4(hp[1], hp[2], hp[3], hp[4]);
}

// ---------------- GEMM: mma.sync fp16, implicit im2col via rowptr table ----------------
extern __shared__ char smem_raw[];

__global__ void __launch_bounds__(256, 1)
bconv_mma(float* __restrict__ out) {
    const int tid = threadIdx.x;
    const int lane = tid & 31;
    const int wid = tid >> 5;
    const int warp_m = wid & 1;      // 2 M-warps (64 rows each)
    const int warp_n = wid >> 1;     // 4 N-warps (64 cols each)
    const int m0 = blockIdx.x * BM;
    const int by = blockIdx.y;
    const int b  = by / JT_PER_IMG;
    const int j0 = (by - b * JT_PER_IMG) * BN;
    const long img_off = (long)b * IN_CHW + j0;

    char* sm = smem_raw;

    float acc[4][8][4];
#pragma unroll
    for (int mi = 0; mi < 4; mi++)
#pragma unroll
        for (int ni = 0; ni < 8; ni++)
#pragma unroll
            for (int e = 0; e < 4; e++) acc[mi][ni][e] = 0.0f;

    // per-thread fixed loader coordinates
    const int a_row = tid >> 2, a_seg = tid & 3;          // A: 2 ops cover 128 rows
    const int b_kr  = tid >> 5, b_seg = tid & 31;         // B: 4 ops cover 32 k-rows

    auto load_stage = [&](int kblk, int st) {
        uint32_t abase = smem_u32(sm + st * STAGE_BYTES);
        uint32_t bbase = abase + A_STAGE;
        int k0 = kblk * BK;
#pragma unroll
        for (int i = 0; i < 2; i++) {               // A: 512 x 16B
            int row = a_row + i * 64;
            const __half* src = g_A + (size_t)(m0 + row) * K_CONV + k0 + a_seg * 8;
            cpa16(abase + row * 80 + a_seg * 16, src);
        }
#pragma unroll
        for (int i = 0; i < 4; i++) {               // B: 1024 x 16B
            int kr = b_kr + i * 8;
            const __half* src = (const __half*)g_rowptr[k0 + kr] + img_off + b_seg * 8;
            cpa16(bbase + kr * 528 + b_seg * 16, src);
        }
    };

    load_stage(0, 0); asm volatile("cp.async.commit_group;");
    load_stage(1, 1); asm volatile("cp.async.commit_group;");
    load_stage(2, 2); asm volatile("cp.async.commit_group;");

    int st = 0;
    for (int it = 0; it < KITERS; it++) {
        asm volatile("cp.async.wait_group 2;" ::: "memory");
        __syncthreads();

        uint32_t abase = smem_u32(sm + st * STAGE_BYTES);
        uint32_t bbase = abase + A_STAGE;

#pragma unroll
        for (int kk = 0; kk < 2; kk++) {
            uint32_t af[4][4], bf[8][2];
#pragma unroll
            for (int mi = 0; mi < 4; mi++) {
                uint32_t addr = abase + (uint32_t)((warp_m * 64 + mi * 16 + (lane & 15)) * 80
                                                   + (kk * 16 + ((lane >> 4) << 3)) * 2);
                asm volatile("ldmatrix.sync.aligned.m8n8.x4.shared.b16 {%0,%1,%2,%3}, [%4];"
                             : "=r"(af[mi][0]), "=r"(af[mi][1]), "=r"(af[mi][2]), "=r"(af[mi][3])
                             : "r"(addr));
            }
#pragma unroll
            for (int ni = 0; ni < 8; ni++) {
                uint32_t addr = bbase + (uint32_t)((kk * 16 + (lane & 15)) * 528
                                                   + (warp_n * 64 + ni * 8) * 2);
                asm volatile("ldmatrix.sync.aligned.m8n8.x2.trans.shared.b16 {%0,%1}, [%2];"
                             : "=r"(bf[ni][0]), "=r"(bf[ni][1]) : "r"(addr));
            }
#pragma unroll
            for (int mi = 0; mi < 4; mi++)
#pragma unroll
                for (int ni = 0; ni < 8; ni++) {
                    asm volatile(
                        "mma.sync.aligned.m16n8k16.row.col.f32.f16.f16.f32 "
                        "{%0,%1,%2,%3}, {%4,%5,%6,%7}, {%8,%9}, {%0,%1,%2,%3};"
                        : "+f"(acc[mi][ni][0]), "+f"(acc[mi][ni][1]),
                          "+f"(acc[mi][ni][2]), "+f"(acc[mi][ni][3])
                        : "r"(af[mi][0]), "r"(af[mi][1]), "r"(af[mi][2]), "r"(af[mi][3]),
                          "r"(bf[ni][0]), "r"(bf[ni][1]));
                }
        }

        __syncthreads();
        if (it + 3 < KITERS) load_stage(it + 3, st);
        asm volatile("cp.async.commit_group;");

        st++; if (st == NSTAGES) st = 0;
    }

    // ---- epilogue: scatter valid pixels to NCHW output ----
#pragma unroll
    for (int mi = 0; mi < 4; mi++) {
        int m_lo = m0 + warp_m * 64 + mi * 16 + (lane >> 2);
#pragma unroll
        for (int ni = 0; ni < 8; ni++) {
            int jb = j0 + warp_n * 64 + ni * 8 + (lane & 3) * 2;
#pragma unroll
            for (int e = 0; e < 4; e++) {
                int mm = m_lo + (e >> 1) * 8;
                int j  = jb + (e & 1);
                int oh = j / IN_HW;
                int ow = j - oh * IN_HW;
                if (ow < OUT_HW && oh < OUT_HW) {
                    out[((size_t)(b * M_TOTAL + mm)) * IMG_PIX + oh * OUT_HW + ow] = acc[mi][ni][e];
                }
            }
        }
    }
}

// ---------------- launcher ----------------
extern "C" void kernel_launch(void* const* d_in, const int* in_sizes, int n_in,
                              void* d_out, int out_size) {
    (void)in_sizes; (void)n_in; (void)out_size;
    const float* x = (const float*)d_in[0];
    const float* w = (const float*)d_in[1];
    float* out = (float*)d_out;

    binarize_kernel<<<(M_TOTAL * K_CONV + 255) / 256, 256>>>(w);
    rowptr_kernel<<<(K_CONV + 255) / 256, 256>>>();
    split_kernel<<<(int)((NX / 8 + 255) / 256), 256>>>(x);

    cudaFuncSetAttribute(bconv_mma, cudaFuncAttributeMaxDynamicSharedMemorySize, DYN_SMEM);
    dim3 grid(M_TOTAL / BM, 32 * JT_PER_IMG);   // (2, 384), M fastest for B-tile L2 reuse
    bconv_mma<<<grid, 256, DYN_SMEM>>>(out);
}

// round 6
// speedup vs baseline: 5.8431x; 1.2795x over previous
#include <cuda_runtime.h>
#include <cuda_fp16.h>
#include <cstdint>

// ---------------- problem geometry ----------------
#define M_TOTAL 256
#define K_CONV  2304          // 256*3*3
#define IN_HW   56
#define IN_PLANE 3136
#define IN_CHW  802816        // 256*56*56
#define NX      25690112      // 32*802816 elements of x
#define OUT_HW  54
#define IMG_PIX 2916
#define JPAD    3072

// ---------------- GEMM tiling ----------------
#define BM 128
#define BN 128
#define BK 32
#define KITERS 72             // 2304/32
#define JT_PER_IMG 24         // 3072/128

#define A_ROW_B 80            // (32+8) halves * 2B
#define B_ROW_B 272           // (128+8) halves * 2B
#define A_STAGE (128 * A_ROW_B)           // 10240 B
#define B_STAGE (BK * B_ROW_B)            // 8704 B
#define STAGE_BYTES (A_STAGE + B_STAGE)   // 18944 B
#define NSTAGES 4
#define DYN_SMEM (NSTAGES * STAGE_BYTES)  // 75776 B

// ---------------- device scratch ----------------
__device__ __half g_A[M_TOTAL * K_CONV];          // [oc][k], sign weights fp16
__device__ __half g_xh[3][NX + 4096];             // fp16(x) shifted by 0,1,2
__device__ unsigned long long g_rowptr[K_CONV];   // per-k base ptr into g_xh

// ---------------- helpers ----------------
__device__ __forceinline__ uint32_t smem_u32(const void* p) {
    uint32_t a;
    asm("{ .reg .u64 t; cvta.to.shared.u64 t, %1; cvt.u32.u64 %0, t; }" : "=r"(a) : "l"(p));
    return a;
}
__device__ __forceinline__ void cpa16(uint32_t dst, const void* src) {
    asm volatile("cp.async.cg.shared.global [%0], [%1], 16;" :: "r"(dst), "l"(src));
}

// ---------------- prep kernels ----------------
__global__ void binarize_kernel(const float* __restrict__ w) {
    int i = blockIdx.x * blockDim.x + threadIdx.x;
    if (i >= M_TOTAL * K_CONV) return;
    float v = w[i];
    float s = (v > 0.0f) ? 1.0f : ((v < 0.0f) ? -1.0f : 0.0f);
    g_A[i] = __float2half_rn(s);
}

__global__ void rowptr_kernel() {
    int k = blockIdx.x * blockDim.x + threadIdx.x;
    if (k >= K_CONV) return;
    int c  = k / 9;
    int r9 = k - c * 9;
    int kh = r9 / 3;
    int kw = r9 - kh * 3;
    g_rowptr[k] = (unsigned long long)(g_xh[kw] + c * IN_PLANE + kh * IN_HW);
}

__global__ void split_kernel(const float* __restrict__ x) {
    long i0 = ((long)blockIdx.x * blockDim.x + threadIdx.x) * 8;
    if (i0 >= NX) return;

    float v[10];
    if (i0 + 12 <= NX) {
        float4 a = *reinterpret_cast<const float4*>(x + i0);
        float4 b = *reinterpret_cast<const float4*>(x + i0 + 4);
        float4 c = *reinterpret_cast<const float4*>(x + i0 + 8);
        v[0]=a.x; v[1]=a.y; v[2]=a.z; v[3]=a.w;
        v[4]=b.x; v[5]=b.y; v[6]=b.z; v[7]=b.w;
        v[8]=c.x; v[9]=c.y;
    } else {
#pragma unroll
        for (int t = 0; t < 10; t++) v[t] = (i0 + t < NX) ? x[i0 + t] : 0.0f;
    }

    uint32_t hp[5], hq[4];
#pragma unroll
    for (int j = 0; j < 5; j++) {
        __half2 h = __floats2half2_rn(v[2*j], v[2*j+1]);
        hp[j] = *reinterpret_cast<uint32_t*>(&h);
    }
#pragma unroll
    for (int j = 0; j < 4; j++) {
        __half2 h = __floats2half2_rn(v[2*j+1], v[2*j+2]);
        hq[j] = *reinterpret_cast<uint32_t*>(&h);
    }

    *reinterpret_cast<uint4*>(&g_xh[0][i0]) = make_uint4(hp[0], hp[1], hp[2], hp[3]);
    *reinterpret_cast<uint4*>(&g_xh[1][i0]) = make_uint4(hq[0], hq[1], hq[2], hq[3]);
    *reinterpret_cast<uint4*>(&g_xh[2][i0]) = make_uint4(hp[1], hp[2], hp[3], hp[4]);
}

// ---------------- GEMM ----------------
extern __shared__ char smem_raw[];

__global__ void __launch_bounds__(256, 2)
bconv_mma(float* __restrict__ out) {
    const int tid = threadIdx.x;
    const int lane = tid & 31;
    const int wid = tid >> 5;
    const int warp_m = wid >> 1;     // 4 M-warps (32 rows each)
    const int warp_n = wid & 1;      // 2 N-warps (64 cols each)
    const int m0 = blockIdx.x * BM;
    const int by = blockIdx.y;
    const int b  = by / JT_PER_IMG;
    const int j0 = (by - b * JT_PER_IMG) * BN;
    const long img_off = (long)b * IN_CHW + j0;

    char* sm = smem_raw;

    float acc[2][8][4];
#pragma unroll
    for (int mi = 0; mi < 2; mi++)
#pragma unroll
        for (int ni = 0; ni < 8; ni++)
#pragma unroll
            for (int e = 0; e < 4; e++) acc[mi][ni][e] = 0.0f;

    // loader coords: A 512 chunks of 16B, B 512 chunks of 16B, 2 each/thread
    const int a_row = tid >> 2, a_seg = tid & 3;    // + i*64 rows
    const int b_kr  = tid >> 4, b_seg = tid & 15;   // + i*16 k-rows

    auto load_stage = [&](int kblk, int st) {
        uint32_t abase = smem_u32(sm + st * STAGE_BYTES);
        uint32_t bbase = abase + A_STAGE;
        int k0 = kblk * BK;
#pragma unroll
        for (int i = 0; i < 2; i++) {
            int row = a_row + i * 64;
            const __half* src = g_A + (size_t)(m0 + row) * K_CONV + k0 + a_seg * 8;
            cpa16(abase + row * A_ROW_B + a_seg * 16, src);
        }
#pragma unroll
        for (int i = 0; i < 2; i++) {
            int kr = b_kr + i * 16;
            const __half* src = (const __half*)g_rowptr[k0 + kr] + img_off + b_seg * 8;
            cpa16(bbase + kr * B_ROW_B + b_seg * 16, src);
        }
    };

    load_stage(0, 0); asm volatile("cp.async.commit_group;");
    load_stage(1, 1); asm volatile("cp.async.commit_group;");
    load_stage(2, 2); asm volatile("cp.async.commit_group;");

#pragma unroll 1
    for (int it = 0; it < KITERS; it++) {
        asm volatile("cp.async.wait_group 2;" ::: "memory");
        __syncthreads();

        // issue next stage loads first (buffer (it+3)%4 == (it-1)%4, free by the
        // barrier above), then compute — loads overlap the MMAs below
        if (it + 3 < KITERS) load_stage(it + 3, (it + 3) & 3);
        asm volatile("cp.async.commit_group;");

        uint32_t abase = smem_u32(sm + (it & 3) * STAGE_BYTES);
        uint32_t bbase = abase + A_STAGE;

#pragma unroll
        for (int kk = 0; kk < 2; kk++) {
            uint32_t af[2][4], bf[8][2];
#pragma unroll
            for (int mi = 0; mi < 2; mi++) {
                uint32_t addr = abase + (uint32_t)((warp_m * 32 + mi * 16 + (lane & 15)) * A_ROW_B
                                                   + (kk * 16 + ((lane >> 4) << 3)) * 2);
                asm volatile("ldmatrix.sync.aligned.m8n8.x4.shared.b16 {%0,%1,%2,%3}, [%4];"
                             : "=r"(af[mi][0]), "=r"(af[mi][1]), "=r"(af[mi][2]), "=r"(af[mi][3])
                             : "r"(addr));
            }
#pragma unroll
            for (int g = 0; g < 4; g++) {           // n16 per x4.trans
                uint32_t addr = bbase + (uint32_t)((kk * 16 + (lane & 15)) * B_ROW_B
                                                   + (warp_n * 64 + g * 16 + ((lane >> 4) << 3)) * 2);
                asm volatile("ldmatrix.sync.aligned.m8n8.x4.trans.shared.b16 {%0,%1,%2,%3}, [%4];"
                             : "=r"(bf[2*g][0]), "=r"(bf[2*g][1]),
                               "=r"(bf[2*g+1][0]), "=r"(bf[2*g+1][1])
                             : "r"(addr));
            }
#pragma unroll
            for (int mi = 0; mi < 2; mi++)
#pragma unroll
                for (int ni = 0; ni < 8; ni++) {
                    asm volatile(
                        "mma.sync.aligned.m16n8k16.row.col.f32.f16.f16.f32 "
                        "{%0,%1,%2,%3}, {%4,%5,%6,%7}, {%8,%9}, {%0,%1,%2,%3};"
                        : "+f"(acc[mi][ni][0]), "+f"(acc[mi][ni][1]),
                          "+f"(acc[mi][ni][2]), "+f"(acc[mi][ni][3])
                        : "r"(af[mi][0]), "r"(af[mi][1]), "r"(af[mi][2]), "r"(af[mi][3]),
                          "r"(bf[ni][0]), "r"(bf[ni][1]));
                }
        }
    }

    // ---- epilogue ----
#pragma unroll
    for (int mi = 0; mi < 2; mi++) {
        int m_lo = m0 + warp_m * 32 + mi * 16 + (lane >> 2);
#pragma unroll
        for (int ni = 0; ni < 8; ni++) {
            int jb = j0 + warp_n * 64 + ni * 8 + (lane & 3) * 2;
#pragma unroll
            for (int e = 0; e < 4; e++) {
                int mm = m_lo + (e >> 1) * 8;
                int j  = jb + (e & 1);
                int oh = j / IN_HW;
                int ow = j - oh * IN_HW;
                if (ow < OUT_HW && oh < OUT_HW) {
                    out[((size_t)(b * M_TOTAL + mm)) * IMG_PIX + oh * OUT_HW + ow] = acc[mi][ni][e];
                }
            }
        }
    }
}

// ---------------- launcher ----------------
extern "C" void kernel_launch(void* const* d_in, const int* in_sizes, int n_in,
                              void* d_out, int out_size) {
    (void)in_sizes; (void)n_in; (void)out_size;
    const float* x = (const float*)d_in[0];
    const float* w = (const float*)d_in[1];
    float* out = (float*)d_out;

    binarize_kernel<<<(M_TOTAL * K_CONV + 255) / 256, 256>>>(w);
    rowptr_kernel<<<(K_CONV + 255) / 256, 256>>>();
    split_kernel<<<(int)((NX / 8 + 255) / 256), 256>>>(x);

    cudaFuncSetAttribute(bconv_mma, cudaFuncAttributeMaxDynamicSharedMemorySize, DYN_SMEM);
    dim3 grid(M_TOTAL / BM, 32 * JT_PER_IMG);   // (2, 768)
    bconv_mma<<<grid, 256, DYN_SMEM>>>(out);
}

// round 7
// speedup vs baseline: 6.0533x; 1.0360x over previous
#include <cuda_runtime.h>
#include <cuda_fp16.h>
#include <cstdint>

// ---------------- problem geometry ----------------
#define M_TOTAL 256
#define K_CONV  2304          // 256*3*3
#define IN_HW   56
#define IN_PLANE 3136
#define IN_CHW  802816        // 256*56*56
#define NX      25690112      // 32*802816 elements of x
#define OUT_HW  54
#define IMG_PIX 2916

// ---------------- GEMM tiling ----------------
#define BM 128
#define BN 128
#define BK 64
#define KITERS 36             // 2304/64
#define JT_PER_IMG 24         // 3072/128

#define A_ROW_B 144           // (64+8) halves * 2B ; 9 chunk columns -> conflict-free ldmatrix
#define B_ROW_B 272           // (128+8) halves * 2B
#define A_STAGE (128 * A_ROW_B)           // 18432 B
#define B_STAGE (BK * B_ROW_B)            // 17408 B
#define STAGE_BYTES (A_STAGE + B_STAGE)   // 35840 B
#define NSTAGES 3
#define DYN_SMEM (NSTAGES * STAGE_BYTES)  // 107520 B

// ---------------- device scratch ----------------
__device__ __half g_A[M_TOTAL * K_CONV];          // [oc][k], sign weights fp16
__device__ __half g_xh[3][NX + 4096];             // fp16(x) shifted by 0,1,2
__device__ unsigned long long g_rowptr[K_CONV];   // per-k base ptr into g_xh

// ---------------- helpers ----------------
__device__ __forceinline__ uint32_t smem_u32(const void* p) {
    uint32_t a;
    asm("{ .reg .u64 t; cvta.to.shared.u64 t, %1; cvt.u32.u64 %0, t; }" : "=r"(a) : "l"(p));
    return a;
}
__device__ __forceinline__ void cpa16(uint32_t dst, const void* src) {
    asm volatile("cp.async.cg.shared.global [%0], [%1], 16;" :: "r"(dst), "l"(src));
}

// ---------------- prep kernels ----------------
__global__ void binarize_kernel(const float* __restrict__ w) {
    int i = blockIdx.x * blockDim.x + threadIdx.x;
    if (i >= M_TOTAL * K_CONV) return;
    float v = w[i];
    float s = (v > 0.0f) ? 1.0f : ((v < 0.0f) ? -1.0f : 0.0f);
    g_A[i] = __float2half_rn(s);
}

__global__ void rowptr_kernel() {
    int k = blockIdx.x * blockDim.x + threadIdx.x;
    if (k >= K_CONV) return;
    int c  = k / 9;
    int r9 = k - c * 9;
    int kh = r9 / 3;
    int kw = r9 - kh * 3;
    g_rowptr[k] = (unsigned long long)(g_xh[kw] + c * IN_PLANE + kh * IN_HW);
}

__global__ void split_kernel(const float* __restrict__ x) {
    long i0 = ((long)blockIdx.x * blockDim.x + threadIdx.x) * 8;
    if (i0 >= NX) return;

    float v[10];
    if (i0 + 12 <= NX) {
        float4 a = *reinterpret_cast<const float4*>(x + i0);
        float4 b = *reinterpret_cast<const float4*>(x + i0 + 4);
        float4 c = *reinterpret_cast<const float4*>(x + i0 + 8);
        v[0]=a.x; v[1]=a.y; v[2]=a.z; v[3]=a.w;
        v[4]=b.x; v[5]=b.y; v[6]=b.z; v[7]=b.w;
        v[8]=c.x; v[9]=c.y;
    } else {
#pragma unroll
        for (int t = 0; t < 10; t++) v[t] = (i0 + t < NX) ? x[i0 + t] : 0.0f;
    }

    uint32_t hp[5], hq[4];
#pragma unroll
    for (int j = 0; j < 5; j++) {
        __half2 h = __floats2half2_rn(v[2*j], v[2*j+1]);
        hp[j] = *reinterpret_cast<uint32_t*>(&h);
    }
#pragma unroll
    for (int j = 0; j < 4; j++) {
        __half2 h = __floats2half2_rn(v[2*j+1], v[2*j+2]);
        hq[j] = *reinterpret_cast<uint32_t*>(&h);
    }

    *reinterpret_cast<uint4*>(&g_xh[0][i0]) = make_uint4(hp[0], hp[1], hp[2], hp[3]);
    *reinterpret_cast<uint4*>(&g_xh[1][i0]) = make_uint4(hq[0], hq[1], hq[2], hq[3]);
    *reinterpret_cast<uint4*>(&g_xh[2][i0]) = make_uint4(hp[1], hp[2], hp[3], hp[4]);
}

// ---------------- GEMM ----------------
extern __shared__ char smem_raw[];

__global__ void __launch_bounds__(256, 2)
bconv_mma(float* __restrict__ out) {
    const int tid = threadIdx.x;
    const int lane = tid & 31;
    const int wid = tid >> 5;
    const int warp_m = wid >> 1;     // 4 M-warps (32 rows each)
    const int warp_n = wid & 1;      // 2 N-warps (64 cols each)
    const int m0 = blockIdx.x * BM;
    const int by = blockIdx.y;
    const int b  = by / JT_PER_IMG;
    const int j0 = (by - b * JT_PER_IMG) * BN;
    const long img_off = (long)b * IN_CHW + j0;

    char* sm = smem_raw;

    float acc[2][8][4];
#pragma unroll
    for (int mi = 0; mi < 2; mi++)
#pragma unroll
        for (int ni = 0; ni < 8; ni++)
#pragma unroll
            for (int e = 0; e < 4; e++) acc[mi][ni][e] = 0.0f;

    // loader coords:
    // A: 128 rows x 8 data chunks of 16B (64 halves); 4 ops: row=(t>>3)+32i, col=t&7
    // B: 64 rows x 16 data chunks;                    4 ops: row=(t>>4)+16i, col=t&15
    const int a_rowq = tid >> 3, a_col = tid & 7;
    const int b_rowq = tid >> 4, b_col = tid & 15;

    auto load_stage = [&](int kblk, int st) {
        uint32_t abase = smem_u32(sm + st * STAGE_BYTES);
        uint32_t bbase = abase + A_STAGE;
        int k0 = kblk * BK;
#pragma unroll
        for (int i = 0; i < 4; i++) {
            int row = a_rowq + i * 32;
            const __half* src = g_A + (size_t)(m0 + row) * K_CONV + k0 + a_col * 8;
            cpa16(abase + row * A_ROW_B + a_col * 16, src);
        }
#pragma unroll
        for (int i = 0; i < 4; i++) {
            int kr = b_rowq + i * 16;
            const __half* src = (const __half*)g_rowptr[k0 + kr] + img_off + b_col * 8;
            cpa16(bbase + kr * B_ROW_B + b_col * 16, src);
        }
    };

    load_stage(0, 0); asm volatile("cp.async.commit_group;");
    load_stage(1, 1); asm volatile("cp.async.commit_group;");

#pragma unroll 1
    for (int it = 0; it < KITERS; it++) {
        asm volatile("cp.async.wait_group 1;" ::: "memory");
        __syncthreads();

        // buffer (it+2)%3 == (it-1)%3 is reusable: every warp passed the barrier
        if (it + 2 < KITERS) load_stage(it + 2, (it + 2) % 3);
        asm volatile("cp.async.commit_group;");

        uint32_t abase = smem_u32(sm + (it % 3) * STAGE_BYTES);
        uint32_t bbase = abase + A_STAGE;

#pragma unroll
        for (int kk = 0; kk < 4; kk++) {
            uint32_t af[2][4], bf[8][2];
#pragma unroll
            for (int mi = 0; mi < 2; mi++) {
                uint32_t addr = abase + (uint32_t)((warp_m * 32 + mi * 16 + (lane & 15)) * A_ROW_B
                                                   + (kk * 16 + ((lane >> 4) << 3)) * 2);
                asm volatile("ldmatrix.sync.aligned.m8n8.x4.shared.b16 {%0,%1,%2,%3}, [%4];"
                             : "=r"(af[mi][0]), "=r"(af[mi][1]), "=r"(af[mi][2]), "=r"(af[mi][3])
                             : "r"(addr));
            }
#pragma unroll
            for (int g = 0; g < 4; g++) {
                uint32_t addr = bbase + (uint32_t)((kk * 16 + (lane & 15)) * B_ROW_B
                                                   + (warp_n * 64 + g * 16 + ((lane >> 4) << 3)) * 2);
                asm volatile("ldmatrix.sync.aligned.m8n8.x4.trans.shared.b16 {%0,%1,%2,%3}, [%4];"
                             : "=r"(bf[2*g][0]), "=r"(bf[2*g][1]),
                               "=r"(bf[2*g+1][0]), "=r"(bf[2*g+1][1])
                             : "r"(addr));
            }
#pragma unroll
            for (int mi = 0; mi < 2; mi++)
#pragma unroll
                for (int ni = 0; ni < 8; ni++) {
                    asm volatile(
                        "mma.sync.aligned.m16n8k16.row.col.f32.f16.f16.f32 "
                        "{%0,%1,%2,%3}, {%4,%5,%6,%7}, {%8,%9}, {%0,%1,%2,%3};"
                        : "+f"(acc[mi][ni][0]), "+f"(acc[mi][ni][1]),
                          "+f"(acc[mi][ni][2]), "+f"(acc[mi][ni][3])
                        : "r"(af[mi][0]), "r"(af[mi][1]), "r"(af[mi][2]), "r"(af[mi][3]),
                          "r"(bf[ni][0]), "r"(bf[ni][1]));
                }
        }
    }

    // ---- epilogue ----
#pragma unroll
    for (int mi = 0; mi < 2; mi++) {
        int m_lo = m0 + warp_m * 32 + mi * 16 + (lane >> 2);
#pragma unroll
        for (int ni = 0; ni < 8; ni++) {
            int jb = j0 + warp_n * 64 + ni * 8 + (lane & 3) * 2;
#pragma unroll
            for (int e = 0; e < 4; e++) {
                int mm = m_lo + (e >> 1) * 8;
                int j  = jb + (e & 1);
                int oh = j / IN_HW;
                int ow = j - oh * IN_HW;
                if (ow < OUT_HW && oh < OUT_HW) {
                    out[((size_t)(b * M_TOTAL + mm)) * IMG_PIX + oh * OUT_HW + ow] = acc[mi][ni][e];
                }
            }
        }
    }
}

// ---------------- launcher ----------------
extern "C" void kernel_launch(void* const* d_in, const int* in_sizes, int n_in,
                              void* d_out, int out_size) {
    (void)in_sizes; (void)n_in; (void)out_size;
    const float* x = (const float*)d_in[0];
    const float* w = (const float*)d_in[1];
    float* out = (float*)d_out;

    binarize_kernel<<<(M_TOTAL * K_CONV + 255) / 256, 256>>>(w);
    rowptr_kernel<<<(K_CONV + 255) / 256, 256>>>();
    split_kernel<<<(int)((NX / 8 + 255) / 256), 256>>>(x);

    cudaFuncSetAttribute(bconv_mma, cudaFuncAttributeMaxDynamicSharedMemorySize, DYN_SMEM);
    dim3 grid(M_TOTAL / BM, 32 * JT_PER_IMG);   // (2, 768)
    bconv_mma<<<grid, 256, DYN_SMEM>>>(out);
}

// round 8
// speedup vs baseline: 6.5931x; 1.0892x over previous
#include <cuda_runtime.h>
#include <cuda_fp16.h>
#include <cstdint>

// ---------------- problem geometry ----------------
#define M_TOTAL 256
#define K_CONV  2304          // 256*3*3
#define IN_HW   56
#define IN_PLANE 3136
#define IN_CHW  802816        // 256*56*56
#define NX      25690112      // 32*802816 elements of x
#define OUT_HW  54
#define IMG_PIX 2916

// ---------------- GEMM tiling ----------------
#define BM 128
#define BN 128
#define BK 64
#define KITERS 36             // 2304/64
#define KQ_TOTAL 144          // 2304/16 k16-groups
#define JT_PER_IMG 24         // 3072/128

#define B_ROW_B 272           // (128+8) halves * 2B
#define B_STAGE (BK * B_ROW_B)            // 17408 B
#define NSTAGES 4
#define DYN_SMEM (NSTAGES * B_STAGE)      // 69632 B

// ---------------- device scratch ----------------
// A in mma fragment layout: [q (k16 group)][G (m16 group)][lane] -> uint4 (a0..a3)
__device__ uint4 g_Af[KQ_TOTAL * 16 * 32];
__device__ __half g_xh[3][NX + 4096];             // fp16(x) shifted by 0,1,2
__device__ unsigned long long g_rowptr[K_CONV];   // per-k base ptr into g_xh

// ---------------- helpers ----------------
__device__ __forceinline__ uint32_t smem_u32(const void* p) {
    uint32_t a;
    asm("{ .reg .u64 t; cvta.to.shared.u64 t, %1; cvt.u32.u64 %0, t; }" : "=r"(a) : "l"(p));
    return a;
}
__device__ __forceinline__ void cpa16(uint32_t dst, const void* src) {
    asm volatile("cp.async.cg.shared.global [%0], [%1], 16;" :: "r"(dst), "l"(src));
}

// ---------------- prep: A fragments (sign weights, fp16, mma layout) ----------------
__device__ __forceinline__ unsigned short sign_h(const float* w, int oc, int k) {
    float v = w[oc * K_CONV + k];
    // fp16 +1 = 0x3C00, -1 = 0xBC00, 0 = 0x0000
    return (v > 0.0f) ? 0x3C00u : ((v < 0.0f) ? 0xBC00u : 0u);
}

__global__ void afrag_kernel(const float* __restrict__ w) {
    int idx = blockIdx.x * blockDim.x + threadIdx.x;
    if (idx >= KQ_TOTAL * 16 * 32) return;
    int lane = idx & 31;
    int G    = (idx >> 5) & 15;
    int q    = idx >> 9;

    int r_lo = G * 16 + (lane >> 2);
    int r_hi = r_lo + 8;
    int c_lo = q * 16 + (lane & 3) * 2;
    int c_hi = c_lo + 8;

    uint32_t v0 = (uint32_t)sign_h(w, r_lo, c_lo) | ((uint32_t)sign_h(w, r_lo, c_lo + 1) << 16);
    uint32_t v1 = (uint32_t)sign_h(w, r_hi, c_lo) | ((uint32_t)sign_h(w, r_hi, c_lo + 1) << 16);
    uint32_t v2 = (uint32_t)sign_h(w, r_lo, c_hi) | ((uint32_t)sign_h(w, r_lo, c_hi + 1) << 16);
    uint32_t v3 = (uint32_t)sign_h(w, r_hi, c_hi) | ((uint32_t)sign_h(w, r_hi, c_hi + 1) << 16);
    g_Af[idx] = make_uint4(v0, v1, v2, v3);
}

__global__ void rowptr_kernel() {
    int k = blockIdx.x * blockDim.x + threadIdx.x;
    if (k >= K_CONV) return;
    int c  = k / 9;
    int r9 = k - c * 9;
    int kh = r9 / 3;
    int kw = r9 - kh * 3;
    g_rowptr[k] = (unsigned long long)(g_xh[kw] + c * IN_PLANE + kh * IN_HW);
}

__global__ void split_kernel(const float* __restrict__ x) {
    long i0 = ((long)blockIdx.x * blockDim.x + threadIdx.x) * 8;
    if (i0 >= NX) return;

    float v[10];
    if (i0 + 12 <= NX) {
        float4 a = *reinterpret_cast<const float4*>(x + i0);
        float4 b = *reinterpret_cast<const float4*>(x + i0 + 4);
        float4 c = *reinterpret_cast<const float4*>(x + i0 + 8);
        v[0]=a.x; v[1]=a.y; v[2]=a.z; v[3]=a.w;
        v[4]=b.x; v[5]=b.y; v[6]=b.z; v[7]=b.w;
        v[8]=c.x; v[9]=c.y;
    } else {
#pragma unroll
        for (int t = 0; t < 10; t++) v[t] = (i0 + t < NX) ? x[i0 + t] : 0.0f;
    }

    uint32_t hp[5], hq[4];
#pragma unroll
    for (int j = 0; j < 5; j++) {
        __half2 h = __floats2half2_rn(v[2*j], v[2*j+1]);
        hp[j] = *reinterpret_cast<uint32_t*>(&h);
    }
#pragma unroll
    for (int j = 0; j < 4; j++) {
        __half2 h = __floats2half2_rn(v[2*j+1], v[2*j+2]);
        hq[j] = *reinterpret_cast<uint32_t*>(&h);
    }

    *reinterpret_cast<uint4*>(&g_xh[0][i0]) = make_uint4(hp[0], hp[1], hp[2], hp[3]);
    *reinterpret_cast<uint4*>(&g_xh[1][i0]) = make_uint4(hq[0], hq[1], hq[2], hq[3]);
    *reinterpret_cast<uint4*>(&g_xh[2][i0]) = make_uint4(hp[1], hp[2], hp[3], hp[4]);
}

// ---------------- GEMM ----------------
extern __shared__ char smem_raw[];

__global__ void __launch_bounds__(256, 2)
bconv_mma(float* __restrict__ out) {
    const int tid = threadIdx.x;
    const int lane = tid & 31;
    const int wid = tid >> 5;
    const int warp_m = wid >> 1;     // 4 M-warps (32 rows each)
    const int warp_n = wid & 1;      // 2 N-warps (64 cols each)
    const int m0 = blockIdx.x * BM;
    const int by = blockIdx.y;
    const int b  = by / JT_PER_IMG;
    const int j0 = (by - b * JT_PER_IMG) * BN;
    const long img_off = (long)b * IN_CHW + j0;

    char* sm = smem_raw;

    // A fragment base for this warp: G = G_base + mi
    const int G_base = (m0 >> 4) + warp_m * 2;
    const uint4* afp = g_Af + lane;   // + (q*16+G)*32

    float acc[2][8][4];
#pragma unroll
    for (int mi = 0; mi < 2; mi++)
#pragma unroll
        for (int ni = 0; ni < 8; ni++)
#pragma unroll
            for (int e = 0; e < 4; e++) acc[mi][ni][e] = 0.0f;

    // B loader: 64 rows x 16 chunks of 16B; 4 ops: row=(t>>4)+16i, col=t&15
    const int b_rowq = tid >> 4, b_col = tid & 15;

    auto load_stage = [&](int kblk, int st) {
        uint32_t bbase = smem_u32(sm + st * B_STAGE);
        int k0 = kblk * BK;
#pragma unroll
        for (int i = 0; i < 4; i++) {
            int kr = b_rowq + i * 16;
            const __half* src = (const __half*)g_rowptr[k0 + kr] + img_off + b_col * 8;
            cpa16(bbase + kr * B_ROW_B + b_col * 16, src);
        }
    };

    load_stage(0, 0); asm volatile("cp.async.commit_group;");
    load_stage(1, 1); asm volatile("cp.async.commit_group;");
    load_stage(2, 2); asm volatile("cp.async.commit_group;");

#pragma unroll 1
    for (int it = 0; it < KITERS; it++) {
        asm volatile("cp.async.wait_group 2;" ::: "memory");
        __syncthreads();

        // buffer (it+3)&3 == (it-1)&3 is reusable: every warp passed the barrier
        if (it + 3 < KITERS) load_stage(it + 3, (it + 3) & 3);
        asm volatile("cp.async.commit_group;");

        uint32_t bbase = smem_u32(sm + (it & 3) * B_STAGE);
        const int q0 = it * 4;

        uint4 af[2][2];           // [buf][mi]
        uint32_t bf[2][8][2];     // [buf][ni][2]

        // preload kk = 0
#pragma unroll
        for (int mi = 0; mi < 2; mi++)
            af[0][mi] = afp[(size_t)((q0 + 0) * 16 + G_base + mi) * 32];
#pragma unroll
        for (int g = 0; g < 4; g++) {
            uint32_t addr = bbase + (uint32_t)((0 * 16 + (lane & 15)) * B_ROW_B
                                               + (warp_n * 64 + g * 16 + ((lane >> 4) << 3)) * 2);
            asm volatile("ldmatrix.sync.aligned.m8n8.x4.trans.shared.b16 {%0,%1,%2,%3}, [%4];"
                         : "=r"(bf[0][2*g][0]), "=r"(bf[0][2*g][1]),
                           "=r"(bf[0][2*g+1][0]), "=r"(bf[0][2*g+1][1])
                         : "r"(addr));
        }

#pragma unroll
        for (int kk = 0; kk < 4; kk++) {
            const int cur = kk & 1, nxt = cur ^ 1;
            if (kk < 3) {
#pragma unroll
                for (int mi = 0; mi < 2; mi++)
                    af[nxt][mi] = afp[(size_t)((q0 + kk + 1) * 16 + G_base + mi) * 32];
#pragma unroll
                for (int g = 0; g < 4; g++) {
                    uint32_t addr = bbase + (uint32_t)(((kk + 1) * 16 + (lane & 15)) * B_ROW_B
                                                       + (warp_n * 64 + g * 16 + ((lane >> 4) << 3)) * 2);
                    asm volatile("ldmatrix.sync.aligned.m8n8.x4.trans.shared.b16 {%0,%1,%2,%3}, [%4];"
                                 : "=r"(bf[nxt][2*g][0]), "=r"(bf[nxt][2*g][1]),
                                   "=r"(bf[nxt][2*g+1][0]), "=r"(bf[nxt][2*g+1][1])
                                 : "r"(addr));
                }
            }
#pragma unroll
            for (int mi = 0; mi < 2; mi++)
#pragma unroll
                for (int ni = 0; ni < 8; ni++) {
                    asm volatile(
                        "mma.sync.aligned.m16n8k16.row.col.f32.f16.f16.f32 "
                        "{%0,%1,%2,%3}, {%4,%5,%6,%7}, {%8,%9}, {%0,%1,%2,%3};"
                        : "+f"(acc[mi][ni][0]), "+f"(acc[mi][ni][1]),
                          "+f"(acc[mi][ni][2]), "+f"(acc[mi][ni][3])
                        : "r"(af[cur][mi].x), "r"(af[cur][mi].y),
                          "r"(af[cur][mi].z), "r"(af[cur][mi].w),
                          "r"(bf[cur][ni][0]), "r"(bf[cur][ni][1]));
                }
        }
    }

    // ---- epilogue ----
#pragma unroll
    for (int mi = 0; mi < 2; mi++) {
        int m_lo = m0 + warp_m * 32 + mi * 16 + (lane >> 2);
#pragma unroll
        for (int ni = 0; ni < 8; ni++) {
            int jb = j0 + warp_n * 64 + ni * 8 + (lane & 3) * 2;
#pragma unroll
            for (int e = 0; e < 4; e++) {
                int mm = m_lo + (e >> 1) * 8;
                int j  = jb + (e & 1);
                int oh = j / IN_HW;
                int ow = j - oh * IN_HW;
                if (ow < OUT_HW && oh < OUT_HW) {
                    out[((size_t)(b * M_TOTAL + mm)) * IMG_PIX + oh * OUT_HW + ow] = acc[mi][ni][e];
                }
            }
        }
    }
}

// ---------------- launcher ----------------
extern "C" void kernel_launch(void* const* d_in, const int* in_sizes, int n_in,
                              void* d_out, int out_size) {
    (void)in_sizes; (void)n_in; (void)out_size;
    const float* x = (const float*)d_in[0];
    const float* w = (const float*)d_in[1];
    float* out = (float*)d_out;

    afrag_kernel<<<(KQ_TOTAL * 16 * 32 + 255) / 256, 256>>>(w);
    rowptr_kernel<<<(K_CONV + 255) / 256, 256>>>();
    split_kernel<<<(int)((NX / 8 + 255) / 256), 256>>>(x);

    cudaFuncSetAttribute(bconv_mma, cudaFuncAttributeMaxDynamicSharedMemorySize, DYN_SMEM);
    dim3 grid(M_TOTAL / BM, 32 * JT_PER_IMG);   // (2, 768)
    bconv_mma<<<grid, 256, DYN_SMEM>>>(out);
}